// round 2
// baseline (speedup 1.0000x reference)
#include <cuda_runtime.h>
#include <math.h>

#define DIM      128
#define NF       64
#define NG       50
#define MAXN     100000
#define CUTOFF_F 10.0f
#define LOG2_F   0.69314718055994531f

// scratch (device globals: allocation-free rule)
__device__ __align__(256) float g_h[(size_t)MAXN * NF];
__device__ __align__(256) float g_agg[(size_t)MAXN * NF];
__device__ int g_idx64;   // 1 if edge_index is int64, 0 if int32

__device__ __forceinline__ float sspf(float v) {
    // softplus(v) - log(2)
    float sp = (v > 15.0f) ? v : log1pf(__expf(v));
    return sp - LOG2_F;
}

// ---------------------------------------------------------------------------
// Kernel 0: probe edge_index dtype. For int64 (LE) indices < 2^31, every odd
// int32 word is 0. 4096 random int32 indices all having odd words zero is
// impossible for this dataset, so this is a safe discriminator.
// ---------------------------------------------------------------------------
__global__ void k_probe(const int* __restrict__ ei, int nwords) {
    __shared__ int any_nonzero;
    if (threadIdx.x == 0) any_nonzero = 0;
    __syncthreads();
    int lim = nwords < 8192 ? nwords : 8192;
    for (int i = threadIdx.x * 2 + 1; i < lim; i += 2 * blockDim.x) {
        if (ei[i] != 0) { any_nonzero = 1; break; }
    }
    __syncthreads();
    if (threadIdx.x == 0) g_idx64 = any_nonzero ? 0 : 1;
}

// ---------------------------------------------------------------------------
// Kernel A: h = x @ conv_lin1_w  ([N,128] @ [128,64]); also zero agg.
// 16 nodes per group, thread handles 2 nodes x 2 cols (weight reuse = 4 FMA/4B)
// ---------------------------------------------------------------------------
__global__ __launch_bounds__(256) void k_lin1(const float* __restrict__ x,
                                              const float* __restrict__ w,
                                              int N) {
    __shared__ __align__(16) float ws[DIM * NF];   // 32 KB
    __shared__ __align__(16) float xs[16 * DIM];   // 8 KB
    for (int i = threadIdx.x; i < DIM * NF; i += 256) ws[i] = w[i];
    __syncthreads();

    const int c2 = (threadIdx.x & 31) * 2;   // col pair
    const int t  = threadIdx.x >> 5;         // 0..7 -> nodes t and t+8

    int nGroups = (N + 15) / 16;
    for (int grp = blockIdx.x; grp < nGroups; grp += gridDim.x) {
        int n0 = grp * 16;
        __syncthreads();
        // stage 16 node rows (2048 floats = 512 float4)
        for (int i = threadIdx.x; i < 512; i += 256) {
            int nl = i >> 5;
            int n  = n0 + nl;
            float4 v = make_float4(0.f, 0.f, 0.f, 0.f);
            if (n < N) v = ((const float4*)(x + (size_t)n * DIM))[i & 31];
            ((float4*)xs)[i] = v;
        }
        __syncthreads();

        float a00 = 0.f, a01 = 0.f, a10 = 0.f, a11 = 0.f;
        #pragma unroll
        for (int kk = 0; kk < 32; kk++) {
            float4 xa = *(const float4*)&xs[t * DIM + 4 * kk];
            float4 xb = *(const float4*)&xs[(t + 8) * DIM + 4 * kk];
            float2 w0 = *(const float2*)&ws[(4 * kk + 0) * NF + c2];
            a00 += xa.x * w0.x; a01 += xa.x * w0.y; a10 += xb.x * w0.x; a11 += xb.x * w0.y;
            float2 w1 = *(const float2*)&ws[(4 * kk + 1) * NF + c2];
            a00 += xa.y * w1.x; a01 += xa.y * w1.y; a10 += xb.y * w1.x; a11 += xb.y * w1.y;
            float2 w2 = *(const float2*)&ws[(4 * kk + 2) * NF + c2];
            a00 += xa.z * w2.x; a01 += xa.z * w2.y; a10 += xb.z * w2.x; a11 += xb.z * w2.y;
            float2 w3 = *(const float2*)&ws[(4 * kk + 3) * NF + c2];
            a00 += xa.w * w3.x; a01 += xa.w * w3.y; a10 += xb.w * w3.x; a11 += xb.w * w3.y;
        }
        int na = n0 + t, nb = n0 + t + 8;
        if (na < N) {
            g_h[(size_t)na * NF + c2]     = a00;
            g_h[(size_t)na * NF + c2 + 1] = a01;
            g_agg[(size_t)na * NF + c2]     = 0.f;
            g_agg[(size_t)na * NF + c2 + 1] = 0.f;
        }
        if (nb < N) {
            g_h[(size_t)nb * NF + c2]     = a10;
            g_h[(size_t)nb * NF + c2 + 1] = a11;
            g_agg[(size_t)nb * NF + c2]     = 0.f;
            g_agg[(size_t)nb * NF + c2 + 1] = 0.f;
        }
    }
}

// ---------------------------------------------------------------------------
// Kernel B: per-edge filter MLP + gather h[src] + scatter-add to agg[dst].
// 1 thread per edge; weights broadcast from smem; vector RED for scatter.
// ---------------------------------------------------------------------------
__global__ __launch_bounds__(256) void k_edge(const void*  __restrict__ ei_raw,
                                              const float* __restrict__ pos,
                                              const float* __restrict__ w1,
                                              const float* __restrict__ b1,
                                              const float* __restrict__ w2,
                                              const float* __restrict__ b2,
                                              int E) {
    __shared__ __align__(16) float w1s[NG * NF];   // 12.8 KB
    __shared__ __align__(16) float w2s[NF * NF];   // 16.4 KB
    __shared__ __align__(16) float b1s[NF];
    __shared__ __align__(16) float b2s[NF];
    for (int i = threadIdx.x; i < NG * NF; i += 256) w1s[i] = w1[i];
    for (int i = threadIdx.x; i < NF * NF; i += 256) w2s[i] = w2[i];
    if (threadIdx.x < NF) { b1s[threadIdx.x] = b1[threadIdx.x]; b2s[threadIdx.x] = b2[threadIdx.x]; }
    __syncthreads();

    const int idx64 = g_idx64;   // uniform
    const int* ei32 = (const int*)ei_raw;
    const long long* ei64 = (const long long*)ei_raw;

    const float delta = CUTOFF_F / (float)(NG - 1);
    const float coeff = -0.5f / (delta * delta);
    const float picut = 3.14159265358979323846f / CUTOFF_F;

    for (int e = blockIdx.x * blockDim.x + threadIdx.x; e < E;
         e += gridDim.x * blockDim.x) {
        int s, d;
        if (idx64) {
            s = (int)ei64[e];
            d = (int)ei64[(size_t)E + e];
        } else {
            s = ei32[e];
            d = ei32[E + e];
        }

        float px = pos[3 * s], py = pos[3 * s + 1], pz = pos[3 * s + 2];
        float vx = pos[3 * d] - px, vy = pos[3 * d + 1] - py, vz = pos[3 * d + 2] - pz;
        float dist = sqrtf(vx * vx + vy * vy + vz * vz);
        float C = 0.5f * (__cosf(dist * picut) + 1.0f);

        // hidden = b1 + edge_attr @ w1
        float4 hid[16];
        #pragma unroll
        for (int jj = 0; jj < 16; jj++) hid[jj] = *(const float4*)&b1s[4 * jj];

        for (int g = 0; g < NG; g++) {
            float t  = dist - (float)g * delta;
            float gv = __expf(coeff * t * t);
            #pragma unroll
            for (int jj = 0; jj < 16; jj++) {
                float4 w = *(const float4*)&w1s[g * NF + 4 * jj];
                hid[jj].x += gv * w.x; hid[jj].y += gv * w.y;
                hid[jj].z += gv * w.z; hid[jj].w += gv * w.w;
            }
        }
        // shifted softplus
        #pragma unroll
        for (int jj = 0; jj < 16; jj++) {
            hid[jj].x = sspf(hid[jj].x); hid[jj].y = sspf(hid[jj].y);
            hid[jj].z = sspf(hid[jj].z); hid[jj].w = sspf(hid[jj].w);
        }

        const float* hrow = g_h + (size_t)s * NF;
        float*       arow = g_agg + (size_t)d * NF;

        for (int kc = 0; kc < 16; kc++) {
            float4 acc = *(const float4*)&b2s[4 * kc];
            #pragma unroll
            for (int jj = 0; jj < 16; jj++) {
                float4 a = hid[jj];
                float4 w;
                w = *(const float4*)&w2s[(4 * jj + 0) * NF + 4 * kc];
                acc.x += a.x * w.x; acc.y += a.x * w.y; acc.z += a.x * w.z; acc.w += a.x * w.w;
                w = *(const float4*)&w2s[(4 * jj + 1) * NF + 4 * kc];
                acc.x += a.y * w.x; acc.y += a.y * w.y; acc.z += a.y * w.z; acc.w += a.y * w.w;
                w = *(const float4*)&w2s[(4 * jj + 2) * NF + 4 * kc];
                acc.x += a.z * w.x; acc.y += a.z * w.y; acc.z += a.z * w.z; acc.w += a.z * w.w;
                w = *(const float4*)&w2s[(4 * jj + 3) * NF + 4 * kc];
                acc.x += a.w * w.x; acc.y += a.w * w.y; acc.z += a.w * w.z; acc.w += a.w * w.w;
            }
            float4 hs = *(const float4*)&hrow[4 * kc];
            float mx = hs.x * (acc.x * C);
            float my = hs.y * (acc.y * C);
            float mz = hs.z * (acc.z * C);
            float mw = hs.w * (acc.w * C);
            asm volatile("red.global.add.v4.f32 [%0], {%1,%2,%3,%4};"
                         :: "l"(arow + 4 * kc), "f"(mx), "f"(my), "f"(mz), "f"(mw)
                         : "memory");
        }
    }
}

// ---------------------------------------------------------------------------
// Kernel C: fused tail.
//   t1 = ssp(agg @ conv_lin2_w + b)
//   t2 = t1 @ int_lin_w + b
//   out = x + relu(t2 @ lin1_w + b)
// 8 nodes/group, 256 threads: c = tid&127, nh = tid>>7 owns 4 nodes.
// All three weight matrices in dynamic smem (~171 KB), 1 block/SM persistent.
// ---------------------------------------------------------------------------
#define TAIL_NODES 8
#define TAIL_SMEM_FLOATS (NF*DIM + DIM*DIM + DIM*DIM + 3*DIM + TAIL_NODES*NF + 2*TAIL_NODES*DIM)

__global__ __launch_bounds__(256) void k_tail(const float* __restrict__ x,
                                              const float* __restrict__ w2c,
                                              const float* __restrict__ b2c,
                                              const float* __restrict__ wint,
                                              const float* __restrict__ bint,
                                              const float* __restrict__ wl1,
                                              const float* __restrict__ bl1,
                                              float* __restrict__ out,
                                              int N) {
    extern __shared__ __align__(16) float sm[];
    float* w2cS  = sm;                       // 8192
    float* wintS = w2cS + NF * DIM;          // 16384
    float* wl1S  = wintS + DIM * DIM;        // 16384
    float* b2s   = wl1S + DIM * DIM;         // 128
    float* bis   = b2s + DIM;                // 128
    float* bls   = bis + DIM;                // 128
    float* aggs  = bls + DIM;                // 8*64
    float* t1s   = aggs + TAIL_NODES * NF;   // 8*128
    float* t2s   = t1s + TAIL_NODES * DIM;   // 8*128

    for (int i = threadIdx.x; i < NF * DIM; i += 256) w2cS[i] = w2c[i];
    for (int i = threadIdx.x; i < DIM * DIM; i += 256) { wintS[i] = wint[i]; wl1S[i] = wl1[i]; }
    for (int i = threadIdx.x; i < DIM; i += 256) { b2s[i] = b2c[i]; bis[i] = bint[i]; bls[i] = bl1[i]; }
    __syncthreads();

    const int c  = threadIdx.x & 127;
    const int nh = threadIdx.x >> 7;   // 0 or 1 -> nodes nh*4 .. nh*4+3

    int nGroups = (N + TAIL_NODES - 1) / TAIL_NODES;
    for (int grp = blockIdx.x; grp < nGroups; grp += gridDim.x) {
        int n0 = grp * TAIL_NODES;
        __syncthreads();
        // stage agg rows: 8*64 floats = 128 float4
        for (int i = threadIdx.x; i < 128; i += 256) {
            int nl = i >> 4;
            int n  = n0 + nl;
            float4 v = make_float4(0.f, 0.f, 0.f, 0.f);
            if (n < N) v = ((const float4*)(g_agg + (size_t)n * NF))[i & 15];
            ((float4*)aggs)[i] = v;
        }
        __syncthreads();

        // ---- stage 1: 64 -> 128, ssp ----
        {
            float s0 = b2s[c], s1 = s0, s2 = s0, s3 = s0;
            const float* a0p = &aggs[(nh * 4 + 0) * NF];
            const float* a1p = &aggs[(nh * 4 + 1) * NF];
            const float* a2p = &aggs[(nh * 4 + 2) * NF];
            const float* a3p = &aggs[(nh * 4 + 3) * NF];
            #pragma unroll
            for (int jj = 0; jj < 16; jj++) {
                float4 q0 = *(const float4*)(a0p + 4 * jj);
                float4 q1 = *(const float4*)(a1p + 4 * jj);
                float4 q2 = *(const float4*)(a2p + 4 * jj);
                float4 q3 = *(const float4*)(a3p + 4 * jj);
                float w;
                w = w2cS[(4 * jj + 0) * DIM + c]; s0 += q0.x * w; s1 += q1.x * w; s2 += q2.x * w; s3 += q3.x * w;
                w = w2cS[(4 * jj + 1) * DIM + c]; s0 += q0.y * w; s1 += q1.y * w; s2 += q2.y * w; s3 += q3.y * w;
                w = w2cS[(4 * jj + 2) * DIM + c]; s0 += q0.z * w; s1 += q1.z * w; s2 += q2.z * w; s3 += q3.z * w;
                w = w2cS[(4 * jj + 3) * DIM + c]; s0 += q0.w * w; s1 += q1.w * w; s2 += q2.w * w; s3 += q3.w * w;
            }
            t1s[(nh * 4 + 0) * DIM + c] = sspf(s0);
            t1s[(nh * 4 + 1) * DIM + c] = sspf(s1);
            t1s[(nh * 4 + 2) * DIM + c] = sspf(s2);
            t1s[(nh * 4 + 3) * DIM + c] = sspf(s3);
        }
        __syncthreads();

        // ---- stage 2: 128 -> 128 (no act) ----
        {
            float s0 = bis[c], s1 = s0, s2 = s0, s3 = s0;
            const float* a0p = &t1s[(nh * 4 + 0) * DIM];
            const float* a1p = &t1s[(nh * 4 + 1) * DIM];
            const float* a2p = &t1s[(nh * 4 + 2) * DIM];
            const float* a3p = &t1s[(nh * 4 + 3) * DIM];
            #pragma unroll
            for (int jj = 0; jj < 32; jj++) {
                float4 q0 = *(const float4*)(a0p + 4 * jj);
                float4 q1 = *(const float4*)(a1p + 4 * jj);
                float4 q2 = *(const float4*)(a2p + 4 * jj);
                float4 q3 = *(const float4*)(a3p + 4 * jj);
                float w;
                w = wintS[(4 * jj + 0) * DIM + c]; s0 += q0.x * w; s1 += q1.x * w; s2 += q2.x * w; s3 += q3.x * w;
                w = wintS[(4 * jj + 1) * DIM + c]; s0 += q0.y * w; s1 += q1.y * w; s2 += q2.y * w; s3 += q3.y * w;
                w = wintS[(4 * jj + 2) * DIM + c]; s0 += q0.z * w; s1 += q1.z * w; s2 += q2.z * w; s3 += q3.z * w;
                w = wintS[(4 * jj + 3) * DIM + c]; s0 += q0.w * w; s1 += q1.w * w; s2 += q2.w * w; s3 += q3.w * w;
            }
            t2s[(nh * 4 + 0) * DIM + c] = s0;
            t2s[(nh * 4 + 1) * DIM + c] = s1;
            t2s[(nh * 4 + 2) * DIM + c] = s2;
            t2s[(nh * 4 + 3) * DIM + c] = s3;
        }
        __syncthreads();

        // ---- stage 3: 128 -> 128, relu + residual ----
        {
            float s0 = bls[c], s1 = s0, s2 = s0, s3 = s0;
            const float* a0p = &t2s[(nh * 4 + 0) * DIM];
            const float* a1p = &t2s[(nh * 4 + 1) * DIM];
            const float* a2p = &t2s[(nh * 4 + 2) * DIM];
            const float* a3p = &t2s[(nh * 4 + 3) * DIM];
            #pragma unroll
            for (int jj = 0; jj < 32; jj++) {
                float4 q0 = *(const float4*)(a0p + 4 * jj);
                float4 q1 = *(const float4*)(a1p + 4 * jj);
                float4 q2 = *(const float4*)(a2p + 4 * jj);
                float4 q3 = *(const float4*)(a3p + 4 * jj);
                float w;
                w = wl1S[(4 * jj + 0) * DIM + c]; s0 += q0.x * w; s1 += q1.x * w; s2 += q2.x * w; s3 += q3.x * w;
                w = wl1S[(4 * jj + 1) * DIM + c]; s0 += q0.y * w; s1 += q1.y * w; s2 += q2.y * w; s3 += q3.y * w;
                w = wl1S[(4 * jj + 2) * DIM + c]; s0 += q0.z * w; s1 += q1.z * w; s2 += q2.z * w; s3 += q3.z * w;
                w = wl1S[(4 * jj + 3) * DIM + c]; s0 += q0.w * w; s1 += q1.w * w; s2 += q2.w * w; s3 += q3.w * w;
            }
            #pragma unroll
            for (int i = 0; i < 4; i++) {
                int n = n0 + nh * 4 + i;
                if (n < N) {
                    float y = (i == 0) ? s0 : (i == 1) ? s1 : (i == 2) ? s2 : s3;
                    y = fmaxf(y, 0.f);
                    out[(size_t)n * DIM + c] = x[(size_t)n * DIM + c] + y;
                }
            }
        }
    }
}

// ---------------------------------------------------------------------------
extern "C" void kernel_launch(void* const* d_in, const int* in_sizes, int n_in,
                              void* d_out, int out_size) {
    const float* x        = (const float*)d_in[0];
    const float* pos      = (const float*)d_in[1];
    const void*  ei       = d_in[2];                 // int32 or int64, probed
    const float* mlp_w1   = (const float*)d_in[3];
    const float* mlp_b1   = (const float*)d_in[4];
    const float* mlp_w2   = (const float*)d_in[5];
    const float* mlp_b2   = (const float*)d_in[6];
    const float* clin1_w  = (const float*)d_in[7];
    const float* clin2_w  = (const float*)d_in[8];
    const float* clin2_b  = (const float*)d_in[9];
    const float* int_w    = (const float*)d_in[10];
    const float* int_b    = (const float*)d_in[11];
    const float* lin1_w   = (const float*)d_in[12];
    const float* lin1_b   = (const float*)d_in[13];
    float* out = (float*)d_out;

    int N = in_sizes[0] / DIM;
    int E = in_sizes[2] / 2;

    const size_t tail_smem = (size_t)TAIL_SMEM_FLOATS * sizeof(float);
    cudaFuncSetAttribute(k_tail, cudaFuncAttributeMaxDynamicSharedMemorySize,
                         (int)tail_smem);

    k_probe<<<1, 256>>>((const int*)ei, 2 * E);
    k_lin1<<<608, 256>>>(x, clin1_w, N);
    k_edge<<<1216, 256>>>(ei, pos, mlp_w1, mlp_b1, mlp_w2, mlp_b2, E);
    k_tail<<<152, 256, tail_smem>>>(x, clin2_w, clin2_b, int_w, int_b,
                                    lin1_w, lin1_b, out, N);
}

// round 4
// speedup vs baseline: 1.0848x; 1.0848x over previous
#include <cuda_runtime.h>
#include <math.h>

#define DIM      128
#define NF       64
#define NG       50
#define MAXN     100000
#define CUTOFF_F 10.0f
#define LOG2_F   0.69314718055994531f

typedef unsigned long long u64;

// scratch (device globals: allocation-free rule)
__device__ __align__(256) float g_h[(size_t)MAXN * NF];
__device__ __align__(256) float g_agg[(size_t)MAXN * NF];
__device__ int g_idx64;   // 1 if edge_index is int64, 0 if int32

// ---- packed f32x2 helpers (FFMA2 path, PTX-only per SASS quickref) ----
__device__ __forceinline__ u64 pack2(float lo, float hi) {
    u64 r; asm("mov.b64 %0,{%1,%2};" : "=l"(r) : "f"(lo), "f"(hi)); return r;
}
__device__ __forceinline__ float2 unpack2(u64 v) {
    float2 f; asm("mov.b64 {%0,%1},%2;" : "=f"(f.x), "=f"(f.y) : "l"(v)); return f;
}
__device__ __forceinline__ u64 fma2(u64 a, u64 b, u64 c) {
    u64 d; asm("fma.rn.f32x2 %0,%1,%2,%3;" : "=l"(d) : "l"(a), "l"(b), "l"(c)); return d;
}
__device__ __forceinline__ u64 mul2(u64 a, u64 b) {
    u64 d; asm("mul.rn.f32x2 %0,%1,%2;" : "=l"(d) : "l"(a), "l"(b)); return d;
}

__device__ __forceinline__ float sspf(float v) {
    // softplus(v) - log2 = log((1+e^v)/2); fast MUFU path (margin vs 1e-3 is huge)
    if (v > 15.0f) return v - LOG2_F;
    return __logf(0.5f + 0.5f * __expf(v));
}

// ---------------------------------------------------------------------------
// Kernel 0: probe edge_index dtype (int64 LE -> all odd words zero).
// ---------------------------------------------------------------------------
__global__ void k_probe(const int* __restrict__ ei, int nwords) {
    __shared__ int any_nonzero;
    if (threadIdx.x == 0) any_nonzero = 0;
    __syncthreads();
    int lim = nwords < 8192 ? nwords : 8192;
    for (int i = threadIdx.x * 2 + 1; i < lim; i += 2 * blockDim.x) {
        if (ei[i] != 0) { any_nonzero = 1; break; }
    }
    __syncthreads();
    if (threadIdx.x == 0) g_idx64 = any_nonzero ? 0 : 1;
}

// ---------------------------------------------------------------------------
// Kernel A: h = x @ conv_lin1_w  ([N,128] @ [128,64]); also zero agg.
// ---------------------------------------------------------------------------
__global__ __launch_bounds__(256) void k_lin1(const float* __restrict__ x,
                                              const float* __restrict__ w,
                                              int N) {
    __shared__ __align__(16) float ws[DIM * NF];
    __shared__ __align__(16) float xs[16 * DIM];
    for (int i = threadIdx.x; i < DIM * NF; i += 256) ws[i] = w[i];
    __syncthreads();

    const int c2 = (threadIdx.x & 31) * 2;
    const int t  = threadIdx.x >> 5;

    int nGroups = (N + 15) / 16;
    for (int grp = blockIdx.x; grp < nGroups; grp += gridDim.x) {
        int n0 = grp * 16;
        __syncthreads();
        for (int i = threadIdx.x; i < 512; i += 256) {
            int nl = i >> 5;
            int n  = n0 + nl;
            float4 v = make_float4(0.f, 0.f, 0.f, 0.f);
            if (n < N) v = ((const float4*)(x + (size_t)n * DIM))[i & 31];
            ((float4*)xs)[i] = v;
        }
        __syncthreads();

        // f32x2 accumulators: (a0x=node a col c2, a0y=node a col c2+1) etc.
        u64 accA = pack2(0.f, 0.f), accB = pack2(0.f, 0.f);
        #pragma unroll
        for (int kk = 0; kk < 32; kk++) {
            float4 xa = *(const float4*)&xs[t * DIM + 4 * kk];
            float4 xb = *(const float4*)&xs[(t + 8) * DIM + 4 * kk];
            u64 w0 = *(const u64*)&ws[(4 * kk + 0) * NF + c2];
            u64 w1 = *(const u64*)&ws[(4 * kk + 1) * NF + c2];
            u64 w2 = *(const u64*)&ws[(4 * kk + 2) * NF + c2];
            u64 w3 = *(const u64*)&ws[(4 * kk + 3) * NF + c2];
            accA = fma2(pack2(xa.x, xa.x), w0, accA);
            accB = fma2(pack2(xb.x, xb.x), w0, accB);
            accA = fma2(pack2(xa.y, xa.y), w1, accA);
            accB = fma2(pack2(xb.y, xb.y), w1, accB);
            accA = fma2(pack2(xa.z, xa.z), w2, accA);
            accB = fma2(pack2(xb.z, xb.z), w2, accB);
            accA = fma2(pack2(xa.w, xa.w), w3, accA);
            accB = fma2(pack2(xb.w, xb.w), w3, accB);
        }
        int na = n0 + t, nb = n0 + t + 8;
        if (na < N) {
            *(u64*)&g_h[(size_t)na * NF + c2]   = accA;
            *(u64*)&g_agg[(size_t)na * NF + c2] = pack2(0.f, 0.f);
        }
        if (nb < N) {
            *(u64*)&g_h[(size_t)nb * NF + c2]   = accB;
            *(u64*)&g_agg[(size_t)nb * NF + c2] = pack2(0.f, 0.f);
        }
    }
}

// ---------------------------------------------------------------------------
// Kernel B: per-edge filter MLP (f32x2) + gather h[src] + RED scatter.
// ---------------------------------------------------------------------------
__global__ __launch_bounds__(256, 2) void k_edge(const void*  __restrict__ ei_raw,
                                                 const float* __restrict__ pos,
                                                 const float* __restrict__ w1,
                                                 const float* __restrict__ b1,
                                                 const float* __restrict__ w2,
                                                 const float* __restrict__ b2,
                                                 int E) {
    __shared__ __align__(16) float w1s[NG * NF];
    __shared__ __align__(16) float w2s[NF * NF];
    __shared__ __align__(16) float b1s[NF];
    __shared__ __align__(16) float b2s[NF];
    for (int i = threadIdx.x; i < NG * NF; i += 256) w1s[i] = w1[i];
    for (int i = threadIdx.x; i < NF * NF; i += 256) w2s[i] = w2[i];
    if (threadIdx.x < NF) { b1s[threadIdx.x] = b1[threadIdx.x]; b2s[threadIdx.x] = b2[threadIdx.x]; }
    __syncthreads();

    const int idx64 = g_idx64;
    const int* ei32 = (const int*)ei_raw;
    const long long* ei64 = (const long long*)ei_raw;

    const float delta = CUTOFF_F / (float)(NG - 1);
    const float coeff = -0.5f / (delta * delta);
    const float picut = 3.14159265358979323846f / CUTOFF_F;

    for (int e = blockIdx.x * blockDim.x + threadIdx.x; e < E;
         e += gridDim.x * blockDim.x) {
        int s, d;
        if (idx64) {
            s = (int)ei64[e];
            d = (int)ei64[(size_t)E + e];
        } else {
            s = ei32[e];
            d = ei32[E + e];
        }

        float px = pos[3 * s], py = pos[3 * s + 1], pz = pos[3 * s + 2];
        float vx = pos[3 * d] - px, vy = pos[3 * d + 1] - py, vz = pos[3 * d + 2] - pz;
        float dist = sqrtf(vx * vx + vy * vy + vz * vz);
        float C = 0.5f * (__cosf(dist * picut) + 1.0f);
        u64 c2 = pack2(C, C);

        // ---- stage 1: hid = b1 + edge_attr @ w1 (packed pairs along filters)
        u64 hid[32];
        #pragma unroll
        for (int j = 0; j < 32; j++) hid[j] = ((const u64*)b1s)[j];

        for (int g = 0; g < NG; g++) {
            float t  = dist - (float)g * delta;
            float gv = __expf(coeff * t * t);
            u64 gv2 = pack2(gv, gv);
            const ulonglong2* wrow = (const ulonglong2*)(w1s + g * NF);
            #pragma unroll
            for (int jj = 0; jj < 16; jj++) {
                ulonglong2 w = wrow[jj];
                hid[2 * jj]     = fma2(gv2, w.x, hid[2 * jj]);
                hid[2 * jj + 1] = fma2(gv2, w.y, hid[2 * jj + 1]);
            }
        }
        // shifted softplus on both halves
        #pragma unroll
        for (int j = 0; j < 32; j++) {
            float2 v = unpack2(hid[j]);
            hid[j] = pack2(sspf(v.x), sspf(v.y));
        }

        const float* hrow = g_h + (size_t)s * NF;
        float*       arow = g_agg + (size_t)d * NF;

        // ---- stage 2 in two halves of 32 output cols (keeps regs modest)
        #pragma unroll
        for (int h = 0; h < 2; h++) {
            u64 acc[16];
            #pragma unroll
            for (int i = 0; i < 16; i++) acc[i] = ((const u64*)(b2s + 32 * h))[i];

            #pragma unroll 4
            for (int j2 = 0; j2 < 32; j2++) {
                float2 aj = unpack2(hid[j2]);
                u64 a0 = pack2(aj.x, aj.x);
                u64 a1 = pack2(aj.y, aj.y);
                const ulonglong2* r0 = (const ulonglong2*)(w2s + (2 * j2) * NF + 32 * h);
                const ulonglong2* r1 = (const ulonglong2*)(w2s + (2 * j2 + 1) * NF + 32 * h);
                #pragma unroll
                for (int kk = 0; kk < 8; kk++) {
                    ulonglong2 wa = r0[kk];
                    acc[2 * kk]     = fma2(a0, wa.x, acc[2 * kk]);
                    acc[2 * kk + 1] = fma2(a0, wa.y, acc[2 * kk + 1]);
                    ulonglong2 wb = r1[kk];
                    acc[2 * kk]     = fma2(a1, wb.x, acc[2 * kk]);
                    acc[2 * kk + 1] = fma2(a1, wb.y, acc[2 * kk + 1]);
                }
            }
            // epilogue: msg = h[src] * (acc * C); scatter via RED.128
            #pragma unroll
            for (int t = 0; t < 8; t++) {
                ulonglong2 hp = *(const ulonglong2*)(hrow + 32 * h + 4 * t);
                u64 m0 = mul2(mul2(c2, hp.x), acc[2 * t]);
                u64 m1 = mul2(mul2(c2, hp.y), acc[2 * t + 1]);
                float2 f0 = unpack2(m0), f1 = unpack2(m1);
                asm volatile("red.global.add.v4.f32 [%0], {%1,%2,%3,%4};"
                             :: "l"(arow + 32 * h + 4 * t),
                                "f"(f0.x), "f"(f0.y), "f"(f1.x), "f"(f1.y)
                             : "memory");
            }
        }
    }
}

// ---------------------------------------------------------------------------
// Kernel C: fused tail, 512 threads, transposed weights, f32x2 over node pairs.
//   t1 = ssp(agg @ conv_lin2_w + b);  t2 = t1 @ int_lin_w + b;
//   out = x + relu(t2 @ lin1_w + b)
// Layouts:
//   weights transposed in smem: wT[c][k] (pad 68 for k=64, 132 for k=128)
//   activations as node-pair float2 rows: actP[pair][k] (8 pairs of 16 nodes)
// ---------------------------------------------------------------------------
#define TAIL_NODES 16
#define TAIL_PAIRS 8
#define W2C_PITCH  68
#define W128_PITCH 132
#define TAIL_SMEM_FLOATS (DIM*W2C_PITCH + 2*DIM*W128_PITCH + 3*DIM \
                          + TAIL_PAIRS*2*NF + 2*TAIL_PAIRS*2*DIM)

__global__ __launch_bounds__(512) void k_tail(const float* __restrict__ x,
                                              const float* __restrict__ w2c,
                                              const float* __restrict__ b2c,
                                              const float* __restrict__ wint,
                                              const float* __restrict__ bint,
                                              const float* __restrict__ wl1,
                                              const float* __restrict__ bl1,
                                              float* __restrict__ out,
                                              int N) {
    extern __shared__ __align__(16) float sm[];
    float* w2cT  = sm;                          // 128*68
    float* wintT = w2cT + DIM * W2C_PITCH;      // 128*132
    float* wl1T  = wintT + DIM * W128_PITCH;    // 128*132
    float* b2s   = wl1T + DIM * W128_PITCH;     // 128
    float* bis   = b2s + DIM;                   // 128
    float* bls   = bis + DIM;                   // 128
    float* aggP  = bls + DIM;                   // 8 pairs * 64 k * 2 = 1024
    float* t1P   = aggP + TAIL_PAIRS * 2 * NF;  // 8 * 128 * 2 = 2048
    float* t2P   = t1P + TAIL_PAIRS * 2 * DIM;  // 2048

    // transpose weights into smem (one-time)
    for (int i = threadIdx.x; i < NF * DIM; i += 512) {
        int k = i >> 7, cc = i & 127;
        w2cT[cc * W2C_PITCH + k] = w2c[i];
    }
    for (int i = threadIdx.x; i < DIM * DIM; i += 512) {
        int k = i >> 7, cc = i & 127;
        wintT[cc * W128_PITCH + k] = wint[i];
        wl1T[cc * W128_PITCH + k]  = wl1[i];
    }
    for (int i = threadIdx.x; i < DIM; i += 512) {
        b2s[i] = b2c[i]; bis[i] = bint[i]; bls[i] = bl1[i];
    }
    __syncthreads();

    const int c  = threadIdx.x & 127;
    const int pg = threadIdx.x >> 7;        // 0..3
    const int p0 = 2 * pg, p1 = 2 * pg + 1; // this thread's node pairs

    int nGroups = (N + TAIL_NODES - 1) / TAIL_NODES;
    for (int grp = blockIdx.x; grp < nGroups; grp += gridDim.x) {
        int n0 = grp * TAIL_NODES;
        __syncthreads();
        // stage agg as pair-interleaved: aggP[p][k] = (agg[2p][k], agg[2p+1][k])
        for (int idx = threadIdx.x; idx < TAIL_PAIRS * NF; idx += 512) {
            int p = idx >> 6, k = idx & 63;
            int na = n0 + 2 * p, nb = na + 1;
            float lo = (na < N) ? g_agg[(size_t)na * NF + k] : 0.f;
            float hi = (nb < N) ? g_agg[(size_t)nb * NF + k] : 0.f;
            ((float2*)aggP)[idx] = make_float2(lo, hi);
        }
        __syncthreads();

        // ---- stage 1: 64 -> 128, ssp ----
        {
            u64 bb = pack2(b2s[c], b2s[c]);
            u64 sA = bb, sB = bb;
            const float* a0r = aggP + p0 * 2 * NF;
            const float* a1r = aggP + p1 * 2 * NF;
            const float* wr  = w2cT + c * W2C_PITCH;
            #pragma unroll
            for (int k0 = 0; k0 < NF; k0 += 4) {
                float4 wv = *(const float4*)(wr + k0);
                u64 w0 = pack2(wv.x, wv.x), w1 = pack2(wv.y, wv.y);
                u64 w2 = pack2(wv.z, wv.z), w3 = pack2(wv.w, wv.w);
                ulonglong2 aA = *(const ulonglong2*)(a0r + 2 * k0);
                ulonglong2 aB = *(const ulonglong2*)(a0r + 2 * k0 + 4);
                sA = fma2(w0, aA.x, sA); sA = fma2(w1, aA.y, sA);
                sA = fma2(w2, aB.x, sA); sA = fma2(w3, aB.y, sA);
                ulonglong2 bA = *(const ulonglong2*)(a1r + 2 * k0);
                ulonglong2 bB = *(const ulonglong2*)(a1r + 2 * k0 + 4);
                sB = fma2(w0, bA.x, sB); sB = fma2(w1, bA.y, sB);
                sB = fma2(w2, bB.x, sB); sB = fma2(w3, bB.y, sB);
            }
            float2 fA = unpack2(sA), fB = unpack2(sB);
            ((float2*)t1P)[p0 * DIM + c] = make_float2(sspf(fA.x), sspf(fA.y));
            ((float2*)t1P)[p1 * DIM + c] = make_float2(sspf(fB.x), sspf(fB.y));
        }
        __syncthreads();

        // ---- stage 2: 128 -> 128 ----
        {
            u64 bb = pack2(bis[c], bis[c]);
            u64 sA = bb, sB = bb;
            const float* a0r = t1P + p0 * 2 * DIM;
            const float* a1r = t1P + p1 * 2 * DIM;
            const float* wr  = wintT + c * W128_PITCH;
            #pragma unroll
            for (int k0 = 0; k0 < DIM; k0 += 4) {
                float4 wv = *(const float4*)(wr + k0);
                u64 w0 = pack2(wv.x, wv.x), w1 = pack2(wv.y, wv.y);
                u64 w2 = pack2(wv.z, wv.z), w3 = pack2(wv.w, wv.w);
                ulonglong2 aA = *(const ulonglong2*)(a0r + 2 * k0);
                ulonglong2 aB = *(const ulonglong2*)(a0r + 2 * k0 + 4);
                sA = fma2(w0, aA.x, sA); sA = fma2(w1, aA.y, sA);
                sA = fma2(w2, aB.x, sA); sA = fma2(w3, aB.y, sA);
                ulonglong2 bA = *(const ulonglong2*)(a1r + 2 * k0);
                ulonglong2 bB = *(const ulonglong2*)(a1r + 2 * k0 + 4);
                sB = fma2(w0, bA.x, sB); sB = fma2(w1, bA.y, sB);
                sB = fma2(w2, bB.x, sB); sB = fma2(w3, bB.y, sB);
            }
            ((u64*)t2P)[p0 * DIM + c] = sA;
            ((u64*)t2P)[p1 * DIM + c] = sB;
        }
        __syncthreads();

        // ---- stage 3: 128 -> 128, relu + residual ----
        {
            u64 bb = pack2(bls[c], bls[c]);
            u64 sA = bb, sB = bb;
            const float* a0r = t2P + p0 * 2 * DIM;
            const float* a1r = t2P + p1 * 2 * DIM;
            const float* wr  = wl1T + c * W128_PITCH;
            #pragma unroll
            for (int k0 = 0; k0 < DIM; k0 += 4) {
                float4 wv = *(const float4*)(wr + k0);
                u64 w0 = pack2(wv.x, wv.x), w1 = pack2(wv.y, wv.y);
                u64 w2 = pack2(wv.z, wv.z), w3 = pack2(wv.w, wv.w);
                ulonglong2 aA = *(const ulonglong2*)(a0r + 2 * k0);
                ulonglong2 aB = *(const ulonglong2*)(a0r + 2 * k0 + 4);
                sA = fma2(w0, aA.x, sA); sA = fma2(w1, aA.y, sA);
                sA = fma2(w2, aB.x, sA); sA = fma2(w3, aB.y, sA);
                ulonglong2 bA = *(const ulonglong2*)(a1r + 2 * k0);
                ulonglong2 bB = *(const ulonglong2*)(a1r + 2 * k0 + 4);
                sB = fma2(w0, bA.x, sB); sB = fma2(w1, bA.y, sB);
                sB = fma2(w2, bB.x, sB); sB = fma2(w3, bB.y, sB);
            }
            float2 fA = unpack2(sA), fB = unpack2(sB);
            int na = n0 + 2 * p0, nb = na + 1;
            int nc2 = n0 + 2 * p1, nd = nc2 + 1;
            if (na < N) out[(size_t)na * DIM + c] = x[(size_t)na * DIM + c] + fmaxf(fA.x, 0.f);
            if (nb < N) out[(size_t)nb * DIM + c] = x[(size_t)nb * DIM + c] + fmaxf(fA.y, 0.f);
            if (nc2 < N) out[(size_t)nc2 * DIM + c] = x[(size_t)nc2 * DIM + c] + fmaxf(fB.x, 0.f);
            if (nd < N) out[(size_t)nd * DIM + c] = x[(size_t)nd * DIM + c] + fmaxf(fB.y, 0.f);
        }
    }
}

// ---------------------------------------------------------------------------
extern "C" void kernel_launch(void* const* d_in, const int* in_sizes, int n_in,
                              void* d_out, int out_size) {
    const float* x        = (const float*)d_in[0];
    const float* pos      = (const float*)d_in[1];
    const void*  ei       = d_in[2];
    const float* mlp_w1   = (const float*)d_in[3];
    const float* mlp_b1   = (const float*)d_in[4];
    const float* mlp_w2   = (const float*)d_in[5];
    const float* mlp_b2   = (const float*)d_in[6];
    const float* clin1_w  = (const float*)d_in[7];
    const float* clin2_w  = (const float*)d_in[8];
    const float* clin2_b  = (const float*)d_in[9];
    const float* int_w    = (const float*)d_in[10];
    const float* int_b    = (const float*)d_in[11];
    const float* lin1_w   = (const float*)d_in[12];
    const float* lin1_b   = (const float*)d_in[13];
    float* out = (float*)d_out;

    int N = in_sizes[0] / DIM;
    int E = in_sizes[2] / 2;

    const size_t tail_smem = (size_t)TAIL_SMEM_FLOATS * sizeof(float);
    cudaFuncSetAttribute(k_tail, cudaFuncAttributeMaxDynamicSharedMemorySize,
                         (int)tail_smem);

    k_probe<<<1, 256>>>((const int*)ei, 2 * E);
    k_lin1<<<608, 256>>>(x, clin1_w, N);
    k_edge<<<1216, 256>>>(ei, pos, mlp_w1, mlp_b1, mlp_w2, mlp_b2, E);
    k_tail<<<152, 512, tail_smem>>>(x, clin2_w, clin2_b, int_w, int_b,
                                    lin1_w, lin1_b, out, N);
}